// round 1
// baseline (speedup 1.0000x reference)
#include <cuda_runtime.h>
#include <cuda_bf16.h>
#include <cstdint>

// Problem constants
#define S_LEN 512
#define BATCH 64
#define D_IN  512
#define H_DIM 1024
#define G4    4096            // 4*H
#define M_ROWS (S_LEN * BATCH)   // 32768

// ---------------- device scratch (no allocations allowed) ----------------
__device__ float g_Wx_p[D_IN * G4];            // 8 MB   permuted Wx
__device__ float g_Wh_p[H_DIM * G4];           // 16 MB  permuted Wh
__device__ float g_bh_p[G4];                   // 16 KB  permuted bias
__device__ float g_gx[(size_t)M_ROWS * G4];    // 512 MB gx = x @ Wx (permuted cols)
__device__ float g_hbuf[2][BATCH * H_DIM];     // ping-pong h
__device__ unsigned g_bar_count;
__device__ unsigned g_bar_gen;

// ---------------- column permutation: new_col = hc*4 + g, old_col = g*1024 + hc ----
__global__ void permute_w(const float* __restrict__ Wx,
                          const float* __restrict__ Wh,
                          const float* __restrict__ bh) {
    int total = (D_IN + H_DIM + 1) * G4;
    for (int i = blockIdx.x * blockDim.x + threadIdx.x; i < total;
         i += gridDim.x * blockDim.x) {
        int r  = i >> 12;        // stacked row: [0,512) Wx, [512,1536) Wh, 1536 bias
        int cn = i & 4095;       // new column
        int hc = cn >> 2;
        int g  = cn & 3;
        int co = g * H_DIM + hc; // old column
        if (r < D_IN) {
            g_Wx_p[r * G4 + cn] = Wx[r * G4 + co];
        } else if (r < D_IN + H_DIM) {
            int k = r - D_IN;
            g_Wh_p[k * G4 + cn] = Wh[k * G4 + co];
        } else {
            g_bh_p[cn] = bh[co];
        }
    }
}

// ---------------- GEMM: g_gx[M_ROWS x 4096] = x[M_ROWS x 512] @ g_Wx_p[512 x 4096]
// 128x128 tile, BK=8, 256 threads, 8x8 microtile per thread.
__global__ __launch_bounds__(256) void gemm_gx(const float* __restrict__ A) {
    __shared__ float As[8][128];   // transposed A tile: As[k][m]
    __shared__ float Bs[8][128];

    const int m0 = blockIdx.y * 128;
    const int n0 = blockIdx.x * 128;
    const int t  = threadIdx.x;
    const int ty = t >> 4;         // 0..15 -> 8 rows each
    const int tx = t & 15;         // 0..15 -> 8 cols each

    const int arow = t >> 1, ak4 = (t & 1) * 4;
    const int brow = t >> 5, bc4 = (t & 31) * 4;

    float acc[8][8];
#pragma unroll
    for (int i = 0; i < 8; ++i)
#pragma unroll
        for (int j = 0; j < 8; ++j) acc[i][j] = 0.f;

    for (int k0 = 0; k0 < D_IN; k0 += 8) {
        float4 av = *(const float4*)&A[(size_t)(m0 + arow) * D_IN + k0 + ak4];
        float4 bv = *(const float4*)&g_Wx_p[(size_t)(k0 + brow) * G4 + n0 + bc4];
        As[ak4 + 0][arow] = av.x;
        As[ak4 + 1][arow] = av.y;
        As[ak4 + 2][arow] = av.z;
        As[ak4 + 3][arow] = av.w;
        *(float4*)&Bs[brow][bc4] = bv;
        __syncthreads();
#pragma unroll
        for (int k = 0; k < 8; ++k) {
            float a[8], b[8];
            *(float4*)(a)     = *(const float4*)&As[k][ty * 8];
            *(float4*)(a + 4) = *(const float4*)&As[k][ty * 8 + 4];
            *(float4*)(b)     = *(const float4*)&Bs[k][tx * 8];
            *(float4*)(b + 4) = *(const float4*)&Bs[k][tx * 8 + 4];
#pragma unroll
            for (int i = 0; i < 8; ++i)
#pragma unroll
                for (int j = 0; j < 8; ++j) acc[i][j] = fmaf(a[i], b[j], acc[i][j]);
        }
        __syncthreads();
    }
#pragma unroll
    for (int i = 0; i < 8; ++i) {
        size_t r = (size_t)(m0 + ty * 8 + i) * G4 + n0 + tx * 8;
        *(float4*)&g_gx[r]     = make_float4(acc[i][0], acc[i][1], acc[i][2], acc[i][3]);
        *(float4*)&g_gx[r + 4] = make_float4(acc[i][4], acc[i][5], acc[i][6], acc[i][7]);
    }
}

// ---------------- software grid barrier (all 128 CTAs co-resident) ----------------
__device__ __forceinline__ void grid_sync(unsigned& bar) {
    __syncthreads();
    if (threadIdx.x == 0) {
        __threadfence();
        unsigned t = atomicAdd(&g_bar_count, 1u);
        bar += 1;
        if (t == gridDim.x - 1u) {
            atomicExch(&g_bar_count, 0u);
            __threadfence();
            atomicAdd(&g_bar_gen, 1u);
        } else {
            while ((int)(atomicAdd(&g_bar_gen, 0u) - bar) < 0) __nanosleep(64);
        }
    }
    __syncthreads();
}

__device__ __forceinline__ float sigm(float x) {
    return 1.0f / (1.0f + __expf(-x));
}

// ---------------- persistent recurrence kernel ----------------
// 128 blocks x 256 threads. Block owns 8 h-columns = 32 contiguous permuted gate
// columns. Per step: gates(64x32) = h(64x1024) @ Wh_p(1024, 32cols) + gx_t + b,
// then LSTM elementwise for the owned (b, hc) pairs; c stays in SMEM all kernel.
__global__ __launch_bounds__(256) void lstm_rec(const float* __restrict__ h0,
                                                const float* __restrict__ c0,
                                                float* __restrict__ out) {
    __shared__ float h_s[64 * 65];      // chunk of h, transposed: h_s[k*65 + b]
    __shared__ float Ws[64 * 32];       // Wh chunk: Ws[k*32 + c]
    __shared__ float gates_s[64 * 32];  // gates tile
    __shared__ float c_s[64 * 8];       // persistent cell state tile

    const int tid = threadIdx.x;
    const int bid = blockIdx.x;
    const int row = tid & 63;   // batch row this thread computes
    const int cg  = tid >> 6;   // column group (8 cols each)
    const int cb  = bid * 32;   // permuted gate-column base
    const int hcb = bid * 8;    // h-column base

    // bias registers (constant across steps)
    float breg[8];
#pragma unroll
    for (int j = 0; j < 8; ++j) breg[j] = g_bh_p[cb + cg * 8 + j];

    // init c tile and our slice of h buffer 0
    for (int p = tid; p < 512; p += 256) {
        int b = p >> 3, hl = p & 7;
        c_s[b * 8 + hl] = c0[b * H_DIM + hcb + hl];
        g_hbuf[0][b * H_DIM + hcb + hl] = h0[b * H_DIM + hcb + hl];
    }

    unsigned bar = 0;
    if (tid == 0) bar = atomicAdd(&g_bar_gen, 0u);  // entry generation (monotonic across replays)
    grid_sync(bar);

    for (int t = 0; t < S_LEN; ++t) {
        const int cur = t & 1;
        const float* hsrc = g_hbuf[cur];
        float acc[8];
#pragma unroll
        for (int j = 0; j < 8; ++j) acc[j] = 0.f;

        for (int kc = 0; kc < 16; ++kc) {
            __syncthreads();
            // load h chunk (64 k x 64 b), transpose into smem; L2 reads (cross-block data)
#pragma unroll
            for (int q = 0; q < 4; ++q) {
                int s  = tid + 256 * q;
                int b  = s >> 4;
                int ko = (s & 15) * 4;
                float4 v = __ldcg((const float4*)(hsrc + b * H_DIM + kc * 64 + ko));
                h_s[(ko + 0) * 65 + b] = v.x;
                h_s[(ko + 1) * 65 + b] = v.y;
                h_s[(ko + 2) * 65 + b] = v.z;
                h_s[(ko + 3) * 65 + b] = v.w;
            }
            // load Wh chunk (64 k x 32 cols)
#pragma unroll
            for (int q = 0; q < 2; ++q) {
                int s  = tid + 256 * q;
                int r  = s >> 3;
                int c4 = (s & 7) * 4;
                *(float4*)&Ws[r * 32 + c4] =
                    *(const float4*)&g_Wh_p[(size_t)(kc * 64 + r) * G4 + cb + c4];
            }
            __syncthreads();
#pragma unroll 16
            for (int kk = 0; kk < 64; ++kk) {
                float  hv = h_s[kk * 65 + row];
                float4 w0 = *(const float4*)&Ws[kk * 32 + cg * 8];
                float4 w1 = *(const float4*)&Ws[kk * 32 + cg * 8 + 4];
                acc[0] = fmaf(hv, w0.x, acc[0]);
                acc[1] = fmaf(hv, w0.y, acc[1]);
                acc[2] = fmaf(hv, w0.z, acc[2]);
                acc[3] = fmaf(hv, w0.w, acc[3]);
                acc[4] = fmaf(hv, w1.x, acc[4]);
                acc[5] = fmaf(hv, w1.y, acc[5]);
                acc[6] = fmaf(hv, w1.z, acc[6]);
                acc[7] = fmaf(hv, w1.w, acc[7]);
            }
        }

        // add gx_t + bias, stage gates in smem
        {
            size_t gxoff = (size_t)(t * BATCH + row) * G4 + cb + cg * 8;
            float4 g0 = *(const float4*)&g_gx[gxoff];
            float4 g1 = *(const float4*)&g_gx[gxoff + 4];
            float* gs = &gates_s[row * 32 + cg * 8];
            gs[0] = acc[0] + g0.x + breg[0];
            gs[1] = acc[1] + g0.y + breg[1];
            gs[2] = acc[2] + g0.z + breg[2];
            gs[3] = acc[3] + g0.w + breg[3];
            gs[4] = acc[4] + g1.x + breg[4];
            gs[5] = acc[5] + g1.y + breg[5];
            gs[6] = acc[6] + g1.z + breg[6];
            gs[7] = acc[7] + g1.w + breg[7];
        }
        __syncthreads();

        // elementwise LSTM update for owned (b, hc) pairs
        float* hdst = g_hbuf[cur ^ 1];
#pragma unroll
        for (int q = 0; q < 2; ++q) {
            int p  = tid + 256 * q;
            int b  = p >> 3;
            int hl = p & 7;
            const float* gs = &gates_s[b * 32 + hl * 4];
            float gi = gs[0], gf = gs[1], gj = gs[2], go = gs[3];
            float fg = sigm(gf + 1.0f);   // FORGET_BIAS = 1.0
            float ig = sigm(gi);
            float og = sigm(go);
            float cnew = c_s[b * 8 + hl] * fg + ig * tanhf(gj);
            c_s[b * 8 + hl] = cnew;
            float hnew = tanhf(cnew) * og;
            hdst[b * H_DIM + hcb + hl] = hnew;
            if (t == S_LEN - 1) {
                out[b * H_DIM + hcb + hl] = hnew;                      // h
                out[BATCH * H_DIM + b * H_DIM + hcb + hl] = cnew;      // c
            }
        }
        grid_sync(bar);
    }
}

// ---------------- launch ----------------
extern "C" void kernel_launch(void* const* d_in, const int* in_sizes, int n_in,
                              void* d_out, int out_size) {
    const float* x  = (const float*)d_in[0];
    const float* h0 = (const float*)d_in[1];
    const float* c0 = (const float*)d_in[2];
    const float* Wx = (const float*)d_in[3];
    const float* Wh = (const float*)d_in[4];
    const float* bh = (const float*)d_in[5];
    float* out = (float*)d_out;

    permute_w<<<2048, 256>>>(Wx, Wh, bh);
    gemm_gx<<<dim3(G4 / 128, M_ROWS / 128), 256>>>(x);
    lstm_rec<<<128, 256>>>(h0, c0, out);
}